// round 1
// baseline (speedup 1.0000x reference)
#include <cuda_runtime.h>
#include <math.h>
#include <float.h>

// Problem geometry (fixed by the reference setup)
#define NMAX 100000
#define HC   128      // H*C
#define NH   4        // heads

// ---------------- scratch (static device allocations; no cudaMalloc) -----
__device__ float g_h    [NMAX * HC];   // x @ W_lin                 (51.2 MB)
__device__ float g_asrc [NMAX * NH];   // per-node, per-head att_src dot
__device__ float g_adst [NMAX * NH];
__device__ float g_m    [NMAX * NH];   // segment max per (dst, head)
__device__ float g_denom[NMAX * NH];   // softmax denominator
__device__ float g_acc  [NMAX * HC];   // un-normalized message accumulator (51.2 MB)
__device__ float g_sum  [HC];          // batchnorm channel sums
__device__ float g_sumsq[HC];
__device__ int   g_is64;               // edge_index dtype flag (1 = int64)

// ---------------- helpers ------------------------------------------------
__device__ __forceinline__ float lrelu02(float v) { return v > 0.f ? v : 0.2f * v; }

// float atomic max via signed/unsigned monotonic mapping.
// Branch on sign BIT (not value) so -0.0 / +0.0 are routed correctly.
__device__ __forceinline__ void atomicMaxF(float* addr, float val) {
    int b = __float_as_int(val);
    if (b >= 0) atomicMax((int*)addr, b);
    else        atomicMin((unsigned int*)addr, (unsigned int)b);
}

// dtype-agnostic edge load (self-loops appended at indices >= E)
__device__ __forceinline__ void load_edge(const void* ei, int i, int E,
                                          int is64, int& src, int& dst) {
    if (i < E) {
        if (is64) {
            const long long* p = (const long long*)ei;
            src = (int)p[i]; dst = (int)p[E + i];
        } else {
            const int* p = (const int*)ei;
            src = p[i];      dst = p[E + i];
        }
    } else {
        src = dst = i - E;
    }
}

// ---------------- kernels ------------------------------------------------

// Probe whether edge_index arrived as int64: int64 values < 2^31 have all-zero
// high words at odd int32 positions. 128 random int32 indices all being zero
// has probability ~1e-640. Deterministic, no host readback.
__global__ void k_detect(const int* ei32) {
    if (threadIdx.x == 0 && blockIdx.x == 0) {
        int all0 = 1;
        for (int k = 0; k < 128; k++)
            if (ei32[2 * k + 1] != 0) { all0 = 0; break; }
        g_is64 = all0;
    }
}

__global__ void k_init(int N) {
    int i = blockIdx.x * blockDim.x + threadIdx.x;
    if (i < N * HC) g_acc[i] = 0.f;
    if (i < N * NH) { g_m[i] = -FLT_MAX; g_denom[i] = 0.f; }
    if (i < HC)     { g_sum[i] = 0.f; g_sumsq[i] = 0.f; }
}

// h = x @ W_lin ; a_src = sum_c h*att_src ; a_dst = sum_c h*att_dst
// One warp per node; lane owns 4 consecutive channels (one head per 8 lanes).
__global__ void k_linear(const float* __restrict__ x,
                         const float* __restrict__ Wl,
                         const float* __restrict__ att_s,
                         const float* __restrict__ att_d, int N) {
    __shared__ float4 Ws[16 * 32];   // W_lin as 16 rows x 32 float4 cols (8 KB)
    int tid = threadIdx.x;
    for (int i = tid; i < 16 * 32; i += blockDim.x)
        Ws[i] = ((const float4*)Wl)[i];
    __syncthreads();

    int node = (blockIdx.x * blockDim.x + tid) >> 5;
    int lane = tid & 31;
    if (node >= N) return;

    const float* xr = x + node * 16;
    float4 acc = make_float4(0.f, 0.f, 0.f, 0.f);
#pragma unroll
    for (int k = 0; k < 16; k++) {
        float xv = xr[k];                   // warp-uniform broadcast load
        float4 w = Ws[k * 32 + lane];
        acc.x += xv * w.x; acc.y += xv * w.y;
        acc.z += xv * w.z; acc.w += xv * w.w;
    }
    ((float4*)g_h)[node * 32 + lane] = acc;

    float4 as = ((const float4*)att_s)[lane];
    float4 ad = ((const float4*)att_d)[lane];
    float ps = acc.x * as.x + acc.y * as.y + acc.z * as.z + acc.w * as.w;
    float pd = acc.x * ad.x + acc.y * ad.y + acc.z * ad.z + acc.w * ad.w;
#pragma unroll
    for (int o = 4; o; o >>= 1) {           // reduce within 8-lane head groups
        ps += __shfl_down_sync(0xffffffffu, ps, o);
        pd += __shfl_down_sync(0xffffffffu, pd, o);
    }
    if ((lane & 7) == 0) {
        int head = lane >> 3;
        g_asrc[node * NH + head] = ps;
        g_adst[node * NH + head] = pd;
    }
}

// Pass 1 over edges: per-(dst,head) segment max of leaky_relu(a_src+a_dst)
__global__ void k_max(const void* __restrict__ ei, int E, int N) {
    int i = blockIdx.x * blockDim.x + threadIdx.x;
    int Et = E + N;
    if (i >= Et) return;
    int is64 = g_is64;
    int src, dst;
    load_edge(ei, i, E, is64, src, dst);
    float4 as = ((const float4*)g_asrc)[src];
    float4 ad = ((const float4*)g_adst)[dst];
    float* mp = g_m + dst * NH;
    atomicMaxF(mp + 0, lrelu02(as.x + ad.x));
    atomicMaxF(mp + 1, lrelu02(as.y + ad.y));
    atomicMaxF(mp + 2, lrelu02(as.z + ad.z));
    atomicMaxF(mp + 3, lrelu02(as.w + ad.w));
}

// Pass 2 over edges (fused): p = exp(e - m[dst]); denom += p;
// acc[dst] += p * h[src]. One WARP per edge; lane owns 4 channels.
__global__ void k_msg(const void* __restrict__ ei, int E, int N) {
    int g = blockIdx.x * blockDim.x + threadIdx.x;
    int edge = g >> 5, lane = g & 31;
    int Et = E + N;
    if (edge >= Et) return;
    int is64 = g_is64;
    int src, dst;
    load_edge(ei, edge, E, is64, src, dst);

    float4 as = ((const float4*)g_asrc)[src];   // warp-uniform
    float4 ad = ((const float4*)g_adst)[dst];
    float4 mv = ((const float4*)g_m)[dst];
    float p0 = __expf(lrelu02(as.x + ad.x) - mv.x);
    float p1 = __expf(lrelu02(as.y + ad.y) - mv.y);
    float p2 = __expf(lrelu02(as.z + ad.z) - mv.z);
    float p3 = __expf(lrelu02(as.w + ad.w) - mv.w);

    if (lane < 4) {
        float pl = lane == 0 ? p0 : lane == 1 ? p1 : lane == 2 ? p2 : p3;
        atomicAdd(g_denom + dst * NH + lane, pl);
    }
    int head = lane >> 3;
    float p = head == 0 ? p0 : head == 1 ? p1 : head == 2 ? p2 : p3;
    float4 hv = ((const float4*)g_h)[src * 32 + lane];
    float4 v  = make_float4(hv.x * p, hv.y * p, hv.z * p, hv.w * p);
    atomicAdd(((float4*)g_acc) + dst * 32 + lane, v);  // sm_90+ vector atomic
}

// Normalize by denom (alpha softmax) and reduce per-channel sum / sumsq.
// blockDim must be 128 (one thread per channel); coalesced row sweeps.
__global__ void k_stats(int N) {
    int c = threadIdx.x;
    float sum = 0.f, sq = 0.f;
    for (int n = blockIdx.x; n < N; n += gridDim.x) {
        float d = g_denom[n * NH + (c >> 5)];
        float v = g_acc[n * HC + c] / d;
        g_acc[n * HC + c] = v;
        sum += v; sq += v * v;
    }
    atomicAdd(&g_sum[c],   sum);
    atomicAdd(&g_sumsq[c], sq);
}

// Gather LUT rows, batchnorm+relu, 128->32 leaky(0.01), 32->1. Block per row.
// (bias_gat cancels exactly inside batchnorm: (h+b - mean-b) = h - mean.)
__global__ void k_final(const int* __restrict__ lut,
                        const float* __restrict__ gamma,
                        const float* __restrict__ beta,
                        const float* __restrict__ W1, const float* __restrict__ b1,
                        const float* __restrict__ W2, const float* __restrict__ b2,
                        float* __restrict__ out, int N) {
    __shared__ float se[128];
    __shared__ float sz[32];
    int c = threadIdx.x;                 // 128 threads
    int node = lut[blockIdx.x];
    float invN = 1.f / (float)N;
    float mean = g_sum[c] * invN;
    float var  = g_sumsq[c] * invN - mean * mean;
    float v = g_acc[node * HC + c];
    float e = (v - mean) * rsqrtf(var + 1e-5f) * gamma[c] + beta[c];
    se[c] = fmaxf(e, 0.f);
    __syncthreads();
    if (c < 32) {
        float acc = b1[c];
#pragma unroll 8
        for (int k = 0; k < 128; k++) acc += se[k] * W1[k * 32 + c];
        sz[c] = acc > 0.f ? acc : 0.01f * acc;
    }
    __syncthreads();
    if (c == 0) {
        float acc = b2[0];
#pragma unroll
        for (int j = 0; j < 32; j++) acc += sz[j] * W2[j];
        out[blockIdx.x] = acc;
    }
}

// ---------------- launch --------------------------------------------------
extern "C" void kernel_launch(void* const* d_in, const int* in_sizes, int n_in,
                              void* d_out, int out_size) {
    const float* x     = (const float*)d_in[0];   // [N,16]
    const void*  ei    = d_in[1];                 // [2,E] int32 or int64
    const int*   lut   = (const int*)d_in[2];     // [NL]
    const float* Wl    = (const float*)d_in[3];   // [16,128]
    const float* att_s = (const float*)d_in[4];   // [4,32]
    const float* att_d = (const float*)d_in[5];   // [4,32]
    // d_in[6] = bias_gat (cancels inside batchnorm; unused)
    const float* gamma = (const float*)d_in[7];
    const float* beta  = (const float*)d_in[8];
    const float* W1    = (const float*)d_in[9];   // [128,32]
    const float* b1    = (const float*)d_in[10];  // [32]
    const float* W2    = (const float*)d_in[11];  // [32,1]
    const float* b2    = (const float*)d_in[12];  // [1]

    int N  = in_sizes[0] / 16;
    int E  = in_sizes[1] / 2;
    int NL = in_sizes[2];
    int Et = E + N;

    k_detect<<<1, 32>>>((const int*)ei);
    k_init  <<<(N * HC + 255) / 256, 256>>>(N);
    k_linear<<<(N * 32 + 255) / 256, 256>>>(x, Wl, att_s, att_d, N);
    k_max   <<<(Et + 255) / 256, 256>>>(ei, E, N);
    k_msg   <<<((long long)Et * 32 + 255) / 256, 256>>>(ei, E, N);
    k_stats <<<512, 128>>>(N);
    k_final <<<NL, 128>>>(lut, gamma, beta, W1, b1, W2, b2, (float*)d_out, N);
}

// round 2
// speedup vs baseline: 1.9243x; 1.9243x over previous
#include <cuda_runtime.h>
#include <math.h>
#include <float.h>

#define NMAX 100000
#define EMAX 1700000
#define HC   128
#define NH   4

// ---------------- static device scratch ----------------------------------
__device__ float g_h    [NMAX * HC];   // x @ W_lin (51.2 MB)
__device__ float g_asrc [NMAX * NH];
__device__ float g_adst [NMAX * NH];
__device__ float g_acc  [NMAX * HC];   // normalized GAT output rows (51.2 MB)
__device__ int   g_deg    [NMAX];      // CSR degree / row_start / cursor
__device__ int   g_rowst  [NMAX];
__device__ int   g_cursor [NMAX];
__device__ int   g_bsum   [128];       // scan block sums
__device__ int   g_esrc [EMAX];        // CSR payload: src index
__device__ float4 g_ep  [EMAX];        // CSR payload: per-head exp weights
__device__ float g_sum  [HC];
__device__ float g_sumsq[HC];
__device__ int   g_is64;

__device__ __forceinline__ float lrelu02(float v) { return v > 0.f ? v : 0.2f * v; }

// ---------------- kernels ------------------------------------------------

// int64-vs-int32 dtype probe: 128 high words all zero => int64.
__global__ void k_detect(const int* ei32) {
    if (threadIdx.x == 0 && blockIdx.x == 0) {
        int all0 = 1;
        for (int k = 0; k < 128; k++)
            if (ei32[2 * k + 1] != 0) { all0 = 0; break; }
        g_is64 = all0;
    }
}

__global__ void k_init(int N) {
    int i = blockIdx.x * blockDim.x + threadIdx.x;
    if (i < N)  g_deg[i] = 0;
    if (i < HC) { g_sum[i] = 0.f; g_sumsq[i] = 0.f; }
}

// h = x @ W_lin ; a_src/a_dst per head. One warp per node.
__global__ void k_linear(const float* __restrict__ x,
                         const float* __restrict__ Wl,
                         const float* __restrict__ att_s,
                         const float* __restrict__ att_d, int N) {
    __shared__ float4 Ws[16 * 32];
    int tid = threadIdx.x;
    for (int i = tid; i < 16 * 32; i += blockDim.x)
        Ws[i] = ((const float4*)Wl)[i];
    __syncthreads();

    int node = (blockIdx.x * blockDim.x + tid) >> 5;
    int lane = tid & 31;
    if (node >= N) return;

    const float* xr = x + node * 16;
    float4 acc = make_float4(0.f, 0.f, 0.f, 0.f);
#pragma unroll
    for (int k = 0; k < 16; k++) {
        float xv = xr[k];
        float4 w = Ws[k * 32 + lane];
        acc.x += xv * w.x; acc.y += xv * w.y;
        acc.z += xv * w.z; acc.w += xv * w.w;
    }
    ((float4*)g_h)[node * 32 + lane] = acc;

    float4 as = ((const float4*)att_s)[lane];
    float4 ad = ((const float4*)att_d)[lane];
    float ps = acc.x * as.x + acc.y * as.y + acc.z * as.z + acc.w * as.w;
    float pd = acc.x * ad.x + acc.y * ad.y + acc.z * ad.z + acc.w * ad.w;
#pragma unroll
    for (int o = 4; o; o >>= 1) {
        ps += __shfl_down_sync(0xffffffffu, ps, o);
        pd += __shfl_down_sync(0xffffffffu, pd, o);
    }
    if ((lane & 7) == 0) {
        int head = lane >> 3;
        g_asrc[node * NH + head] = ps;
        g_adst[node * NH + head] = pd;
    }
}

// degree histogram over explicit edges (self-loops handled in k_agg)
__global__ void k_hist(const void* __restrict__ ei, int E) {
    int i = blockIdx.x * blockDim.x + threadIdx.x;
    if (i >= E) return;
    int dst;
    if (g_is64) dst = (int)((const long long*)ei)[E + i];
    else        dst = ((const int*)ei)[E + i];
    atomicAdd(&g_deg[dst], 1);
}

// 3-kernel exclusive scan of g_deg -> g_rowst (+ cursor copy)
__global__ void k_scanA(int N) {
    __shared__ int s[1024];
    int i = blockIdx.x * 1024 + threadIdx.x;
    int v = (i < N) ? g_deg[i] : 0;
    s[threadIdx.x] = v;
    __syncthreads();
#pragma unroll
    for (int off = 1; off < 1024; off <<= 1) {
        int t = (threadIdx.x >= off) ? s[threadIdx.x - off] : 0;
        __syncthreads();
        s[threadIdx.x] += t;
        __syncthreads();
    }
    if (i < N) g_rowst[i] = s[threadIdx.x] - v;      // exclusive within block
    if (threadIdx.x == 1023) g_bsum[blockIdx.x] = s[1023];
}
__global__ void k_scanB(int nb) {
    if (threadIdx.x == 0 && blockIdx.x == 0) {
        int a = 0;
        for (int i = 0; i < nb; i++) { int t = g_bsum[i]; g_bsum[i] = a; a += t; }
    }
}
__global__ void k_scanC(int N) {
    int i = blockIdx.x * blockDim.x + threadIdx.x;
    if (i >= N) return;
    int r = g_rowst[i] + g_bsum[i >> 10];
    g_rowst[i] = r;
    g_cursor[i] = r;
}

// scatter edges into CSR buckets with precomputed per-head exp weights
__global__ void k_scatter(const void* __restrict__ ei, int E) {
    int i = blockIdx.x * blockDim.x + threadIdx.x;
    if (i >= E) return;
    int src, dst;
    if (g_is64) {
        const long long* p = (const long long*)ei;
        src = (int)p[i]; dst = (int)p[E + i];
    } else {
        const int* p = (const int*)ei;
        src = p[i]; dst = p[E + i];
    }
    float4 as = ((const float4*)g_asrc)[src];
    float4 ad = ((const float4*)g_adst)[dst];
    float4 pw;
    pw.x = __expf(lrelu02(as.x + ad.x));
    pw.y = __expf(lrelu02(as.y + ad.y));
    pw.z = __expf(lrelu02(as.z + ad.z));
    pw.w = __expf(lrelu02(as.w + ad.w));
    int pos = atomicAdd(&g_cursor[dst], 1);
    g_esrc[pos] = src;
    g_ep[pos]   = pw;
}

// one warp per dst: gather-aggregate (no atomics on acc), softmax-normalize,
// fused batchnorm channel-stat reduction. blockDim = 256.
__global__ void k_agg(int N) {
    __shared__ float ssum[HC], ssq[HC];
    int tid = threadIdx.x;
    if (tid < HC) { ssum[tid] = 0.f; ssq[tid] = 0.f; }
    __syncthreads();

    int node = (blockIdx.x * blockDim.x + tid) >> 5;
    int lane = tid & 31;
    if (node < N) {
        int head = lane >> 3;
        // self-loop term
        float4 as = ((const float4*)g_asrc)[node];
        float4 ad = ((const float4*)g_adst)[node];
        float ev = head == 0 ? as.x + ad.x : head == 1 ? as.y + ad.y
                 : head == 2 ? as.z + ad.z : as.w + ad.w;
        float pself = __expf(lrelu02(ev));
        float4 hd = ((const float4*)g_h)[node * 32 + lane];
        float4 acc = make_float4(pself * hd.x, pself * hd.y,
                                 pself * hd.z, pself * hd.w);
        float dsum = pself;

        int j   = g_rowst[node];
        int end = j + g_deg[node];
        for (; j < end; j++) {
            int src  = g_esrc[j];                       // warp-uniform
            float4 p4 = g_ep[j];                        // warp-uniform
            float p = head == 0 ? p4.x : head == 1 ? p4.y
                    : head == 2 ? p4.z : p4.w;
            float4 hv = ((const float4*)g_h)[src * 32 + lane];
            acc.x += p * hv.x; acc.y += p * hv.y;
            acc.z += p * hv.z; acc.w += p * hv.w;
            dsum  += p;
        }
        float inv = 1.f / dsum;
        float4 o = make_float4(acc.x * inv, acc.y * inv,
                               acc.z * inv, acc.w * inv);
        ((float4*)g_acc)[node * 32 + lane] = o;

        int c = lane * 4;
        atomicAdd(&ssum[c + 0], o.x); atomicAdd(&ssq[c + 0], o.x * o.x);
        atomicAdd(&ssum[c + 1], o.y); atomicAdd(&ssq[c + 1], o.y * o.y);
        atomicAdd(&ssum[c + 2], o.z); atomicAdd(&ssq[c + 2], o.z * o.z);
        atomicAdd(&ssum[c + 3], o.w); atomicAdd(&ssq[c + 3], o.w * o.w);
    }
    __syncthreads();
    if (tid < HC) {
        atomicAdd(&g_sum[tid],   ssum[tid]);
        atomicAdd(&g_sumsq[tid], ssq[tid]);
    }
}

// gather LUT rows, batchnorm+relu, MLP 128->32->1. bias_gat cancels in BN.
__global__ void k_final(const int* __restrict__ lut,
                        const float* __restrict__ gamma,
                        const float* __restrict__ beta,
                        const float* __restrict__ W1, const float* __restrict__ b1,
                        const float* __restrict__ W2, const float* __restrict__ b2,
                        float* __restrict__ out, int N) {
    __shared__ float se[128];
    __shared__ float sz[32];
    int c = threadIdx.x;
    int node = lut[blockIdx.x];
    float invN = 1.f / (float)N;
    float mean = g_sum[c] * invN;
    float var  = g_sumsq[c] * invN - mean * mean;
    float v = g_acc[node * HC + c];
    float e = (v - mean) * rsqrtf(var + 1e-5f) * gamma[c] + beta[c];
    se[c] = fmaxf(e, 0.f);
    __syncthreads();
    if (c < 32) {
        float acc = b1[c];
#pragma unroll 8
        for (int k = 0; k < 128; k++) acc += se[k] * W1[k * 32 + c];
        sz[c] = acc > 0.f ? acc : 0.01f * acc;
    }
    __syncthreads();
    if (c == 0) {
        float acc = b2[0];
#pragma unroll
        for (int j = 0; j < 32; j++) acc += sz[j] * W2[j];
        out[blockIdx.x] = acc;
    }
}

// ---------------- launch --------------------------------------------------
extern "C" void kernel_launch(void* const* d_in, const int* in_sizes, int n_in,
                              void* d_out, int out_size) {
    const float* x     = (const float*)d_in[0];
    const void*  ei    = d_in[1];
    const int*   lut   = (const int*)d_in[2];
    const float* Wl    = (const float*)d_in[3];
    const float* att_s = (const float*)d_in[4];
    const float* att_d = (const float*)d_in[5];
    const float* gamma = (const float*)d_in[7];
    const float* beta  = (const float*)d_in[8];
    const float* W1    = (const float*)d_in[9];
    const float* b1    = (const float*)d_in[10];
    const float* W2    = (const float*)d_in[11];
    const float* b2    = (const float*)d_in[12];

    int N  = in_sizes[0] / 16;
    int E  = in_sizes[1] / 2;
    int NL = in_sizes[2];
    int nbScan = (N + 1023) / 1024;

    k_detect <<<1, 32>>>((const int*)ei);
    k_init   <<<(N + 255) / 256, 256>>>(N);
    k_linear <<<(N * 32 + 255) / 256, 256>>>(x, Wl, att_s, att_d, N);
    k_hist   <<<(E + 255) / 256, 256>>>(ei, E);
    k_scanA  <<<nbScan, 1024>>>(N);
    k_scanB  <<<1, 32>>>(nbScan);
    k_scanC  <<<(N + 255) / 256, 256>>>(N);
    k_scatter<<<(E + 255) / 256, 256>>>(ei, E);
    k_agg    <<<(N * 32 + 255) / 256, 256>>>(N);
    k_final  <<<NL, 128>>>(lut, gamma, beta, W1, b1, W2, b2, (float*)d_out, N);
}

// round 3
// speedup vs baseline: 2.0526x; 1.0666x over previous
#include <cuda_runtime.h>
#include <math.h>
#include <float.h>

#define NMAX 100000
#define EMAX 1700000
#define HC   128
#define NH   4

// ---------------- static device scratch ----------------------------------
__device__ float g_h    [NMAX * HC];   // x @ W_lin (51.2 MB)
__device__ float g_asrc [NMAX * NH];
__device__ float g_adst [NMAX * NH];
__device__ float g_acc  [NMAX * HC];   // GAT rows (only LUT rows written)
__device__ int   g_deg    [NMAX];
__device__ int   g_rowst  [NMAX];
__device__ int   g_cursor [NMAX];
__device__ int   g_isl    [NMAX];      // 1 if node is a LUT row
__device__ int   g_bsum   [128];
__device__ int   g_esrc [EMAX];
__device__ float4 g_ep  [EMAX];
__device__ float g_sum  [HC];
__device__ float g_sumsq[HC];
__device__ int   g_is64;

__device__ __forceinline__ float lrelu02(float v) { return v > 0.f ? v : 0.2f * v; }

// ---------------- kernels ------------------------------------------------

// init + dtype probe (128 zero high-words => int64)
__global__ void k_init(const int* ei32, int N) {
    int i = blockIdx.x * blockDim.x + threadIdx.x;
    if (i < N)  { g_deg[i] = 0; g_isl[i] = 0; }
    if (i < HC) { g_sum[i] = 0.f; g_sumsq[i] = 0.f; }
    if (i == 0) {
        int all0 = 1;
        for (int k = 0; k < 128; k++)
            if (ei32[2 * k + 1] != 0) { all0 = 0; break; }
        g_is64 = all0;
    }
}

__global__ void k_mark(const int* __restrict__ lut, int NL) {
    int i = blockIdx.x * blockDim.x + threadIdx.x;
    if (i < NL) g_isl[lut[i]] = 1;
}

// h = x @ W_lin ; per-head attention dots. One warp per node.
__global__ void k_linear(const float* __restrict__ x,
                         const float* __restrict__ Wl,
                         const float* __restrict__ att_s,
                         const float* __restrict__ att_d, int N) {
    __shared__ float4 Ws[16 * 32];
    int tid = threadIdx.x;
    for (int i = tid; i < 16 * 32; i += blockDim.x)
        Ws[i] = ((const float4*)Wl)[i];
    __syncthreads();

    int node = (blockIdx.x * blockDim.x + tid) >> 5;
    int lane = tid & 31;
    if (node >= N) return;

    const float* xr = x + node * 16;
    float4 acc = make_float4(0.f, 0.f, 0.f, 0.f);
#pragma unroll
    for (int k = 0; k < 16; k++) {
        float xv = xr[k];
        float4 w = Ws[k * 32 + lane];
        acc.x += xv * w.x; acc.y += xv * w.y;
        acc.z += xv * w.z; acc.w += xv * w.w;
    }
    ((float4*)g_h)[node * 32 + lane] = acc;

    float4 as = ((const float4*)att_s)[lane];
    float4 ad = ((const float4*)att_d)[lane];
    float ps = acc.x * as.x + acc.y * as.y + acc.z * as.z + acc.w * as.w;
    float pd = acc.x * ad.x + acc.y * ad.y + acc.z * ad.z + acc.w * ad.w;
#pragma unroll
    for (int o = 4; o; o >>= 1) {
        ps += __shfl_down_sync(0xffffffffu, ps, o);
        pd += __shfl_down_sync(0xffffffffu, pd, o);
    }
    if ((lane & 7) == 0) {
        int head = lane >> 3;
        g_asrc[node * NH + head] = ps;
        g_adst[node * NH + head] = pd;
    }
}

__global__ void k_hist(const void* __restrict__ ei, int E) {
    int i = blockIdx.x * blockDim.x + threadIdx.x;
    if (i >= E) return;
    int dst;
    if (g_is64) dst = (int)((const long long*)ei)[E + i];
    else        dst = ((const int*)ei)[E + i];
    atomicAdd(&g_deg[dst], 1);
}

// 3-kernel exclusive scan of g_deg -> g_rowst
__global__ void k_scanA(int N) {
    __shared__ int s[1024];
    int i = blockIdx.x * 1024 + threadIdx.x;
    int v = (i < N) ? g_deg[i] : 0;
    s[threadIdx.x] = v;
    __syncthreads();
#pragma unroll
    for (int off = 1; off < 1024; off <<= 1) {
        int t = (threadIdx.x >= off) ? s[threadIdx.x - off] : 0;
        __syncthreads();
        s[threadIdx.x] += t;
        __syncthreads();
    }
    if (i < N) g_rowst[i] = s[threadIdx.x] - v;
    if (threadIdx.x == 1023) g_bsum[blockIdx.x] = s[1023];
}
__global__ void k_scanB(int nb) {
    if (threadIdx.x == 0 && blockIdx.x == 0) {
        int a = 0;
        for (int i = 0; i < nb; i++) { int t = g_bsum[i]; g_bsum[i] = a; a += t; }
    }
}
__global__ void k_scanC(int N) {
    int i = blockIdx.x * blockDim.x + threadIdx.x;
    if (i >= N) return;
    int r = g_rowst[i] + g_bsum[i >> 10];
    g_rowst[i] = r;
    g_cursor[i] = r;
}

// scatter edges into CSR buckets with precomputed per-head exp weights
__global__ void k_scatter(const void* __restrict__ ei, int E) {
    int i = blockIdx.x * blockDim.x + threadIdx.x;
    if (i >= E) return;
    int src, dst;
    if (g_is64) {
        const long long* p = (const long long*)ei;
        src = (int)p[i]; dst = (int)p[E + i];
    } else {
        const int* p = (const int*)ei;
        src = p[i]; dst = p[E + i];
    }
    float4 as = ((const float4*)g_asrc)[src];
    float4 ad = ((const float4*)g_adst)[dst];
    float4 pw;
    pw.x = __expf(lrelu02(as.x + ad.x));
    pw.y = __expf(lrelu02(as.y + ad.y));
    pw.z = __expf(lrelu02(as.z + ad.z));
    pw.w = __expf(lrelu02(as.w + ad.w));
    int pos = atomicAdd(&g_cursor[dst], 1);
    g_esrc[pos] = src;
    g_ep[pos]   = pw;
}

// one warp per dst. Unroll-by-4 software pipeline: 4 independent 128B
// gathers in flight (MLP>=4) instead of one dependent chain per edge.
__global__ void k_agg(int N) {
    __shared__ float ssum[HC], ssq[HC];
    int tid = threadIdx.x;
    if (tid < HC) { ssum[tid] = 0.f; ssq[tid] = 0.f; }
    __syncthreads();

    int node = (blockIdx.x * blockDim.x + tid) >> 5;
    int lane = tid & 31;
    if (node < N) {
        int head = lane >> 3;
        // self-loop
        float4 as = ((const float4*)g_asrc)[node];
        float4 ad = ((const float4*)g_adst)[node];
        float ev = head == 0 ? as.x + ad.x : head == 1 ? as.y + ad.y
                 : head == 2 ? as.z + ad.z : as.w + ad.w;
        float pself = __expf(lrelu02(ev));
        float4 hd = ((const float4*)g_h)[node * 32 + lane];
        float4 acc = make_float4(pself * hd.x, pself * hd.y,
                                 pself * hd.z, pself * hd.w);
        float dsum = pself;

        const float4* gh = (const float4*)g_h;
        int j   = g_rowst[node];
        int end = j + g_deg[node];

        for (; j + 4 <= end; j += 4) {
            int s0 = g_esrc[j],     s1 = g_esrc[j + 1];
            int s2 = g_esrc[j + 2], s3 = g_esrc[j + 3];
            float4 q0 = g_ep[j],     q1 = g_ep[j + 1];
            float4 q2 = g_ep[j + 2], q3 = g_ep[j + 3];
            // 4 independent gathers
            float4 h0 = gh[s0 * 32 + lane];
            float4 h1 = gh[s1 * 32 + lane];
            float4 h2 = gh[s2 * 32 + lane];
            float4 h3 = gh[s3 * 32 + lane];
            float p0 = head == 0 ? q0.x : head == 1 ? q0.y : head == 2 ? q0.z : q0.w;
            float p1 = head == 0 ? q1.x : head == 1 ? q1.y : head == 2 ? q1.z : q1.w;
            float p2 = head == 0 ? q2.x : head == 1 ? q2.y : head == 2 ? q2.z : q2.w;
            float p3 = head == 0 ? q3.x : head == 1 ? q3.y : head == 2 ? q3.z : q3.w;
            acc.x += p0 * h0.x; acc.y += p0 * h0.y; acc.z += p0 * h0.z; acc.w += p0 * h0.w;
            acc.x += p1 * h1.x; acc.y += p1 * h1.y; acc.z += p1 * h1.z; acc.w += p1 * h1.w;
            acc.x += p2 * h2.x; acc.y += p2 * h2.y; acc.z += p2 * h2.z; acc.w += p2 * h2.w;
            acc.x += p3 * h3.x; acc.y += p3 * h3.y; acc.z += p3 * h3.z; acc.w += p3 * h3.w;
            dsum += p0 + p1 + p2 + p3;
        }
        for (; j < end; j++) {
            int src  = g_esrc[j];
            float4 q = g_ep[j];
            float p = head == 0 ? q.x : head == 1 ? q.y : head == 2 ? q.z : q.w;
            float4 hv = gh[src * 32 + lane];
            acc.x += p * hv.x; acc.y += p * hv.y;
            acc.z += p * hv.z; acc.w += p * hv.w;
            dsum  += p;
        }
        float inv = 1.f / dsum;
        float4 o = make_float4(acc.x * inv, acc.y * inv,
                               acc.z * inv, acc.w * inv);
        if (g_isl[node])                             // only LUT rows re-read
            ((float4*)g_acc)[node * 32 + lane] = o;

        int c = lane * 4;
        atomicAdd(&ssum[c + 0], o.x); atomicAdd(&ssq[c + 0], o.x * o.x);
        atomicAdd(&ssum[c + 1], o.y); atomicAdd(&ssq[c + 1], o.y * o.y);
        atomicAdd(&ssum[c + 2], o.z); atomicAdd(&ssq[c + 2], o.z * o.z);
        atomicAdd(&ssum[c + 3], o.w); atomicAdd(&ssq[c + 3], o.w * o.w);
    }
    __syncthreads();
    if (tid < HC) {
        atomicAdd(&g_sum[tid],   ssum[tid]);
        atomicAdd(&g_sumsq[tid], ssq[tid]);
    }
}

// gather LUT rows, batchnorm+relu, MLP 128->32->1. (bias_gat cancels in BN.)
__global__ void k_final(const int* __restrict__ lut,
                        const float* __restrict__ gamma,
                        const float* __restrict__ beta,
                        const float* __restrict__ W1, const float* __restrict__ b1,
                        const float* __restrict__ W2, const float* __restrict__ b2,
                        float* __restrict__ out, int N) {
    __shared__ float se[128];
    __shared__ float sz[32];
    int c = threadIdx.x;
    int node = lut[blockIdx.x];
    float invN = 1.f / (float)N;
    float mean = g_sum[c] * invN;
    float var  = g_sumsq[c] * invN - mean * mean;
    float v = g_acc[node * HC + c];
    float e = (v - mean) * rsqrtf(var + 1e-5f) * gamma[c] + beta[c];
    se[c] = fmaxf(e, 0.f);
    __syncthreads();
    if (c < 32) {
        float acc = b1[c];
#pragma unroll 8
        for (int k = 0; k < 128; k++) acc += se[k] * W1[k * 32 + c];
        sz[c] = acc > 0.f ? acc : 0.01f * acc;
    }
    __syncthreads();
    if (c == 0) {
        float acc = b2[0];
#pragma unroll
        for (int j = 0; j < 32; j++) acc += sz[j] * W2[j];
        out[blockIdx.x] = acc;
    }
}

// ---------------- launch --------------------------------------------------
extern "C" void kernel_launch(void* const* d_in, const int* in_sizes, int n_in,
                              void* d_out, int out_size) {
    const float* x     = (const float*)d_in[0];
    const void*  ei    = d_in[1];
    const int*   lut   = (const int*)d_in[2];
    const float* Wl    = (const float*)d_in[3];
    const float* att_s = (const float*)d_in[4];
    const float* att_d = (const float*)d_in[5];
    const float* gamma = (const float*)d_in[7];
    const float* beta  = (const float*)d_in[8];
    const float* W1    = (const float*)d_in[9];
    const float* b1    = (const float*)d_in[10];
    const float* W2    = (const float*)d_in[11];
    const float* b2    = (const float*)d_in[12];

    int N  = in_sizes[0] / 16;
    int E  = in_sizes[1] / 2;
    int NL = in_sizes[2];
    int nbScan = (N + 1023) / 1024;

    k_init   <<<(N + 255) / 256, 256>>>((const int*)ei, N);
    k_mark   <<<(NL + 255) / 256, 256>>>(lut, NL);
    k_linear <<<(N * 32 + 255) / 256, 256>>>(x, Wl, att_s, att_d, N);
    k_hist   <<<(E + 255) / 256, 256>>>(ei, E);
    k_scanA  <<<nbScan, 1024>>>(N);
    k_scanB  <<<1, 32>>>(nbScan);
    k_scanC  <<<(N + 255) / 256, 256>>>(N);
    k_scatter<<<(E + 255) / 256, 256>>>(ei, E);
    k_agg    <<<(N * 32 + 255) / 256, 256>>>(N);
    k_final  <<<NL, 128>>>(lut, gamma, beta, W1, b1, W2, b2, (float*)d_out, N);
}

// round 4
// speedup vs baseline: 2.4879x; 1.2121x over previous
#include <cuda_runtime.h>
#include <cuda_fp16.h>
#include <math.h>
#include <float.h>

#define NMAX 100000
#define EMAX 1700000
#define HC   128
#define NH   4

// ---------------- static device scratch ----------------------------------
__device__ __half g_hh  [NMAX * HC];   // x @ W_lin in fp16 (25.6 MB)
__device__ float g_asrc [NMAX * NH];
__device__ float g_adst [NMAX * NH];
__device__ float g_acc  [NMAX * HC];   // GAT rows (only LUT rows written)
__device__ int   g_deg    [NMAX];
__device__ int   g_rowst  [NMAX];
__device__ int   g_cursor [NMAX];
__device__ int   g_isl    [NMAX];
__device__ int   g_bsum   [128];
__device__ int   g_esrc [EMAX];        // CSR payload: src only (4B/edge)
__device__ float g_sum  [HC];
__device__ float g_sumsq[HC];
__device__ int   g_is64;

__device__ __forceinline__ float lrelu02(float v) { return v > 0.f ? v : 0.2f * v; }
__device__ __forceinline__ float hsel(float4 v, int head) {
    return head == 0 ? v.x : head == 1 ? v.y : head == 2 ? v.z : v.w;
}

// ---------------- kernels ------------------------------------------------

// init + LUT mark + dtype probe (128 zero high-words => int64)
__global__ void k_init(const int* ei32, const int* __restrict__ lut,
                       int N, int NL) {
    int i = blockIdx.x * blockDim.x + threadIdx.x;
    if (i < N)  { g_deg[i] = 0; g_isl[i] = 0; }
    if (i < HC) { g_sum[i] = 0.f; g_sumsq[i] = 0.f; }
    if (i < NL) g_isl[lut[i]] = 1;
    if (i == 0) {
        int all0 = 1;
        for (int k = 0; k < 128; k++)
            if (ei32[2 * k + 1] != 0) { all0 = 0; break; }
        g_is64 = all0;
    }
}

// Fused: blocks [0,nLin) do h = x@W_lin (+ attention dots, fp16 store);
// blocks [nLin, ...) do the degree histogram. Overlaps store-bound GEMV
// with latency-bound histogram.
__global__ void k_linhist(const float* __restrict__ x,
                          const float* __restrict__ Wl,
                          const float* __restrict__ att_s,
                          const float* __restrict__ att_d,
                          const void* __restrict__ ei,
                          int N, int E, int nLin) {
    int tid = threadIdx.x;
    if (blockIdx.x >= nLin) {
        int i = (blockIdx.x - nLin) * blockDim.x + tid;
        if (i < E) {
            int dst;
            if (g_is64) dst = (int)((const long long*)ei)[E + i];
            else        dst = ((const int*)ei)[E + i];
            atomicAdd(&g_deg[dst], 1);
        }
        return;
    }

    __shared__ float4 Ws[16 * 32];
    for (int i = tid; i < 16 * 32; i += blockDim.x)
        Ws[i] = ((const float4*)Wl)[i];
    __syncthreads();

    int node = (blockIdx.x * blockDim.x + tid) >> 5;
    int lane = tid & 31;
    if (node >= N) return;

    const float* xr = x + node * 16;
    float4 acc = make_float4(0.f, 0.f, 0.f, 0.f);
#pragma unroll
    for (int k = 0; k < 16; k++) {
        float xv = xr[k];
        float4 w = Ws[k * 32 + lane];
        acc.x += xv * w.x; acc.y += xv * w.y;
        acc.z += xv * w.z; acc.w += xv * w.w;
    }
    // fp16 store: 4 halves per lane (8B)
    __half2 p01 = __floats2half2_rn(acc.x, acc.y);
    __half2 p23 = __floats2half2_rn(acc.z, acc.w);
    uint2 pack;
    pack.x = *(unsigned int*)&p01;
    pack.y = *(unsigned int*)&p23;
    ((uint2*)g_hh)[node * 32 + lane] = pack;

    float4 as = ((const float4*)att_s)[lane];
    float4 ad = ((const float4*)att_d)[lane];
    float ps = acc.x * as.x + acc.y * as.y + acc.z * as.z + acc.w * as.w;
    float pd = acc.x * ad.x + acc.y * ad.y + acc.z * ad.z + acc.w * ad.w;
#pragma unroll
    for (int o = 4; o; o >>= 1) {
        ps += __shfl_down_sync(0xffffffffu, ps, o);
        pd += __shfl_down_sync(0xffffffffu, pd, o);
    }
    if ((lane & 7) == 0) {
        int head = lane >> 3;
        g_asrc[node * NH + head] = ps;
        g_adst[node * NH + head] = pd;
    }
}

// exclusive scan of g_deg -> g_rowst (3 launches; B is a parallel 1-block scan)
__global__ void k_scanA(int N) {
    __shared__ int s[1024];
    int i = blockIdx.x * 1024 + threadIdx.x;
    int v = (i < N) ? g_deg[i] : 0;
    s[threadIdx.x] = v;
    __syncthreads();
#pragma unroll
    for (int off = 1; off < 1024; off <<= 1) {
        int t = (threadIdx.x >= off) ? s[threadIdx.x - off] : 0;
        __syncthreads();
        s[threadIdx.x] += t;
        __syncthreads();
    }
    if (i < N) g_rowst[i] = s[threadIdx.x] - v;
    if (threadIdx.x == 1023) g_bsum[blockIdx.x] = s[1023];
}
__global__ void k_scanB(int nb) {   // nb <= 128; one block of 128 threads
    __shared__ int s[128];
    int t = threadIdx.x;
    int v = (t < nb) ? g_bsum[t] : 0;
    s[t] = v;
    __syncthreads();
#pragma unroll
    for (int off = 1; off < 128; off <<= 1) {
        int u = (t >= off) ? s[t - off] : 0;
        __syncthreads();
        s[t] += u;
        __syncthreads();
    }
    if (t < nb) g_bsum[t] = s[t] - v;   // exclusive
}
__global__ void k_scanC(int N) {
    int i = blockIdx.x * blockDim.x + threadIdx.x;
    if (i >= N) return;
    int r = g_rowst[i] + g_bsum[i >> 10];
    g_rowst[i] = r;
    g_cursor[i] = r;
}

// scatter: only src index (4B) per edge into CSR bucket
__global__ void k_scatter(const void* __restrict__ ei, int E) {
    int i = blockIdx.x * blockDim.x + threadIdx.x;
    if (i >= E) return;
    int src, dst;
    if (g_is64) {
        const long long* p = (const long long*)ei;
        src = (int)p[i]; dst = (int)p[E + i];
    } else {
        const int* p = (const int*)ei;
        src = p[i]; dst = p[E + i];
    }
    int pos = atomicAdd(&g_cursor[dst], 1);
    g_esrc[pos] = src;
}

// one warp per dst node: gather h[src] (fp16), recompute softmax weights,
// normalize, fused batchnorm stats. Unroll-4 for MLP.
__global__ void k_agg(int N) {
    __shared__ float ssum[HC], ssq[HC];
    int tid = threadIdx.x;
    if (tid < HC) { ssum[tid] = 0.f; ssq[tid] = 0.f; }
    __syncthreads();

    int node = (blockIdx.x * blockDim.x + tid) >> 5;
    int lane = tid & 31;
    if (node < N) {
        int head = lane >> 3;
        const float4* asrc4 = (const float4*)g_asrc;
        const uint2*  gh    = (const uint2*)g_hh;

        float4 adv = ((const float4*)g_adst)[node];
        float advh = hsel(adv, head);

        // self-loop
        float4 asl = asrc4[node];
        float pself = __expf(lrelu02(hsel(asl, head) + advh));
        uint2 rs = gh[node * 32 + lane];
        float2 s01 = __half22float2(*(__half2*)&rs.x);
        float2 s23 = __half22float2(*(__half2*)&rs.y);
        float4 acc = make_float4(pself * s01.x, pself * s01.y,
                                 pself * s23.x, pself * s23.y);
        float dsum = pself;

        int j   = g_rowst[node];
        int end = j + g_deg[node];

        for (; j + 4 <= end; j += 4) {
            int s0 = g_esrc[j],     s1 = g_esrc[j + 1];
            int s2 = g_esrc[j + 2], s3 = g_esrc[j + 3];
            float4 a0 = asrc4[s0], a1 = asrc4[s1];
            float4 a2 = asrc4[s2], a3 = asrc4[s3];
            uint2 r0 = gh[s0 * 32 + lane];
            uint2 r1 = gh[s1 * 32 + lane];
            uint2 r2 = gh[s2 * 32 + lane];
            uint2 r3 = gh[s3 * 32 + lane];
            float p0 = __expf(lrelu02(hsel(a0, head) + advh));
            float p1 = __expf(lrelu02(hsel(a1, head) + advh));
            float p2 = __expf(lrelu02(hsel(a2, head) + advh));
            float p3 = __expf(lrelu02(hsel(a3, head) + advh));
            float2 f01, f23;
            f01 = __half22float2(*(__half2*)&r0.x); f23 = __half22float2(*(__half2*)&r0.y);
            acc.x += p0 * f01.x; acc.y += p0 * f01.y; acc.z += p0 * f23.x; acc.w += p0 * f23.y;
            f01 = __half22float2(*(__half2*)&r1.x); f23 = __half22float2(*(__half2*)&r1.y);
            acc.x += p1 * f01.x; acc.y += p1 * f01.y; acc.z += p1 * f23.x; acc.w += p1 * f23.y;
            f01 = __half22float2(*(__half2*)&r2.x); f23 = __half22float2(*(__half2*)&r2.y);
            acc.x += p2 * f01.x; acc.y += p2 * f01.y; acc.z += p2 * f23.x; acc.w += p2 * f23.y;
            f01 = __half22float2(*(__half2*)&r3.x); f23 = __half22float2(*(__half2*)&r3.y);
            acc.x += p3 * f01.x; acc.y += p3 * f01.y; acc.z += p3 * f23.x; acc.w += p3 * f23.y;
            dsum += p0 + p1 + p2 + p3;
        }
        for (; j < end; j++) {
            int s = g_esrc[j];
            float4 a = asrc4[s];
            uint2 r = gh[s * 32 + lane];
            float p = __expf(lrelu02(hsel(a, head) + advh));
            float2 f01 = __half22float2(*(__half2*)&r.x);
            float2 f23 = __half22float2(*(__half2*)&r.y);
            acc.x += p * f01.x; acc.y += p * f01.y;
            acc.z += p * f23.x; acc.w += p * f23.y;
            dsum += p;
        }
        float inv = 1.f / dsum;
        float4 o = make_float4(acc.x * inv, acc.y * inv,
                               acc.z * inv, acc.w * inv);
        if (g_isl[node])
            ((float4*)g_acc)[node * 32 + lane] = o;

        int c = lane * 4;
        atomicAdd(&ssum[c + 0], o.x); atomicAdd(&ssq[c + 0], o.x * o.x);
        atomicAdd(&ssum[c + 1], o.y); atomicAdd(&ssq[c + 1], o.y * o.y);
        atomicAdd(&ssum[c + 2], o.z); atomicAdd(&ssq[c + 2], o.z * o.z);
        atomicAdd(&ssum[c + 3], o.w); atomicAdd(&ssq[c + 3], o.w * o.w);
    }
    __syncthreads();
    if (tid < HC) {
        atomicAdd(&g_sum[tid],   ssum[tid]);
        atomicAdd(&g_sumsq[tid], ssq[tid]);
    }
}

// gather LUT rows, batchnorm+relu, MLP 128->32->1. (bias_gat cancels in BN.)
__global__ void k_final(const int* __restrict__ lut,
                        const float* __restrict__ gamma,
                        const float* __restrict__ beta,
                        const float* __restrict__ W1, const float* __restrict__ b1,
                        const float* __restrict__ W2, const float* __restrict__ b2,
                        float* __restrict__ out, int N) {
    __shared__ float se[128];
    __shared__ float sz[32];
    int c = threadIdx.x;
    int node = lut[blockIdx.x];
    float invN = 1.f / (float)N;
    float mean = g_sum[c] * invN;
    float var  = g_sumsq[c] * invN - mean * mean;
    float v = g_acc[node * HC + c];
    float e = (v - mean) * rsqrtf(var + 1e-5f) * gamma[c] + beta[c];
    se[c] = fmaxf(e, 0.f);
    __syncthreads();
    if (c < 32) {
        float acc = b1[c];
#pragma unroll 8
        for (int k = 0; k < 128; k++) acc += se[k] * W1[k * 32 + c];
        sz[c] = acc > 0.f ? acc : 0.01f * acc;
    }
    __syncthreads();
    if (c == 0) {
        float acc = b2[0];
#pragma unroll
        for (int j = 0; j < 32; j++) acc += sz[j] * W2[j];
        out[blockIdx.x] = acc;
    }
}

// ---------------- launch --------------------------------------------------
extern "C" void kernel_launch(void* const* d_in, const int* in_sizes, int n_in,
                              void* d_out, int out_size) {
    const float* x     = (const float*)d_in[0];
    const void*  ei    = d_in[1];
    const int*   lut   = (const int*)d_in[2];
    const float* Wl    = (const float*)d_in[3];
    const float* att_s = (const float*)d_in[4];
    const float* att_d = (const float*)d_in[5];
    const float* gamma = (const float*)d_in[7];
    const float* beta  = (const float*)d_in[8];
    const float* W1    = (const float*)d_in[9];
    const float* b1    = (const float*)d_in[10];
    const float* W2    = (const float*)d_in[11];
    const float* b2    = (const float*)d_in[12];

    int N  = in_sizes[0] / 16;
    int E  = in_sizes[1] / 2;
    int NL = in_sizes[2];
    int nbScan = (N + 1023) / 1024;
    int nLin   = (N * 32 + 255) / 256;
    int nHist  = (E + 255) / 256;

    k_init   <<<(N + 255) / 256, 256>>>((const int*)ei, lut, N, NL);
    k_linhist<<<nLin + nHist, 256>>>(x, Wl, att_s, att_d, ei, N, E, nLin);
    k_scanA  <<<nbScan, 1024>>>(N);
    k_scanB  <<<1, 128>>>(nbScan);
    k_scanC  <<<(N + 255) / 256, 256>>>(N);
    k_scatter<<<(E + 255) / 256, 256>>>(ei, E);
    k_agg    <<<(N * 32 + 255) / 256, 256>>>(N);
    k_final  <<<NL, 128>>>(lut, gamma, beta, W1, b1, W2, b2, (float*)d_out, N);
}

// round 5
// speedup vs baseline: 3.7831x; 1.5206x over previous
#include <cuda_runtime.h>
#include <cuda_fp16.h>
#include <math.h>
#include <float.h>

#define NMAX 100000
#define EMAX 1700000
#define HC   128
#define NH   4

// ---------------- static device scratch ----------------------------------
__device__ __half g_x16 [NMAX * 16];   // x in fp16 (3.2 MB, L2-resident)
__device__ float g_asrc [NMAX * NH];
__device__ float g_adst [NMAX * NH];
__device__ float g_accum[NMAX * 64];   // per-node, per-head x-space accums
__device__ float g_den  [NMAX * NH];   // softmax denominators
__device__ float g_embed[1024 * HC];   // LUT rows of GAT output (512 KB)
__device__ int   g_deg    [NMAX];
__device__ int   g_rowst  [NMAX];
__device__ int   g_cursor [NMAX];
__device__ int   g_isl    [NMAX];      // lut position + 1, or 0
__device__ int   g_bsum   [128];
__device__ int   g_esrc [EMAX];        // CSR payload: src only
__device__ float g_ws   [64];          // W @ att_src  (4 heads x 16)
__device__ float g_wd   [64];          // W @ att_dst
__device__ float g_sum  [HC];
__device__ float g_sumsq[HC];
__device__ int   g_is64;

__device__ __forceinline__ float lrelu02(float v) { return v > 0.f ? v : 0.2f * v; }

// ---------------- kernels ------------------------------------------------

// init + ws/wd precompute + dtype probe
__global__ void k_init(const int* ei32, const float* __restrict__ Wl,
                       const float* __restrict__ att_s,
                       const float* __restrict__ att_d, int N) {
    int i = blockIdx.x * blockDim.x + threadIdx.x;
    if (i < N)  { g_deg[i] = 0; g_isl[i] = 0; }
    if (i < HC) { g_sum[i] = 0.f; g_sumsq[i] = 0.f; }
    if (blockIdx.x == 0 && threadIdx.x < 128) {
        int t = threadIdx.x;
        int h = (t & 63) >> 4, k = t & 15;
        const float* att = (t < 64) ? att_s : att_d;
        float s = 0.f;
        for (int c = 0; c < 32; c++)
            s += Wl[k * HC + h * 32 + c] * att[h * 32 + c];
        if (t < 64) g_ws[t] = s; else g_wd[t - 64] = s;
    }
    if (i == 0) {
        int all0 = 1;
        for (int k = 0; k < 128; k++)
            if (ei32[2 * k + 1] != 0) { all0 = 0; break; }
        g_is64 = all0;
    }
}

// Fused: blocks [0,nLin): per-thread node -> x16 + asrc/adst.
//        blocks [nLin,..): degree histogram.
__global__ void k_linhist(const float* __restrict__ x,
                          const void* __restrict__ ei,
                          int N, int E, int nLin) {
    int tid = threadIdx.x;
    if (blockIdx.x >= nLin) {
        int i = (blockIdx.x - nLin) * blockDim.x + tid;
        if (i < E) {
            int dst;
            if (g_is64) dst = (int)((const long long*)ei)[E + i];
            else        dst = ((const int*)ei)[E + i];
            atomicAdd(&g_deg[dst], 1);
        }
        return;
    }
    __shared__ float sws[64], swd[64];
    if (tid < 64)  sws[tid] = g_ws[tid];
    else if (tid < 128) swd[tid - 64] = g_wd[tid - 64];
    __syncthreads();

    int node = blockIdx.x * blockDim.x + tid;
    if (node >= N) return;
    float xf[16];
    const float4* xr = (const float4*)(x + node * 16);
#pragma unroll
    for (int q = 0; q < 4; q++) {
        float4 v = xr[q];
        xf[q * 4 + 0] = v.x; xf[q * 4 + 1] = v.y;
        xf[q * 4 + 2] = v.z; xf[q * 4 + 3] = v.w;
    }
    // fp16 copy of x (two 16B stores)
    __half hx[16];
#pragma unroll
    for (int k = 0; k < 16; k++) hx[k] = __float2half_rn(xf[k]);
    ((uint4*)g_x16)[node * 2 + 0] = *(uint4*)&hx[0];
    ((uint4*)g_x16)[node * 2 + 1] = *(uint4*)&hx[8];
    // attention dots via rank-16 projection
    float4 as, ad;
    float* asp = (float*)&as; float* adp = (float*)&ad;
#pragma unroll
    for (int h = 0; h < 4; h++) {
        float ss = 0.f, sd = 0.f;
#pragma unroll
        for (int k = 0; k < 16; k++) {
            ss += xf[k] * sws[h * 16 + k];
            sd += xf[k] * swd[h * 16 + k];
        }
        asp[h] = ss; adp[h] = sd;
    }
    ((float4*)g_asrc)[node] = as;
    ((float4*)g_adst)[node] = ad;
}

// exclusive scan of g_deg -> g_rowst
__global__ void k_scanA(int N) {
    __shared__ int s[1024];
    int i = blockIdx.x * 1024 + threadIdx.x;
    int v = (i < N) ? g_deg[i] : 0;
    s[threadIdx.x] = v;
    __syncthreads();
#pragma unroll
    for (int off = 1; off < 1024; off <<= 1) {
        int t = (threadIdx.x >= off) ? s[threadIdx.x - off] : 0;
        __syncthreads();
        s[threadIdx.x] += t;
        __syncthreads();
    }
    if (i < N) g_rowst[i] = s[threadIdx.x] - v;
    if (threadIdx.x == 1023) g_bsum[blockIdx.x] = s[1023];
}
__global__ void k_scanB(int nb) {
    __shared__ int s[128];
    int t = threadIdx.x;
    int v = (t < nb) ? g_bsum[t] : 0;
    s[t] = v;
    __syncthreads();
#pragma unroll
    for (int off = 1; off < 128; off <<= 1) {
        int u = (t >= off) ? s[t - off] : 0;
        __syncthreads();
        s[t] += u;
        __syncthreads();
    }
    if (t < nb) g_bsum[t] = s[t] - v;
}
__global__ void k_scanC(const int* __restrict__ lut, int N, int NL) {
    int i = blockIdx.x * blockDim.x + threadIdx.x;
    if (i < NL) g_isl[lut[i]] = i + 1;      // mark LUT positions
    if (i >= N) return;
    int r = g_rowst[i] + g_bsum[i >> 10];
    g_rowst[i] = r;
    g_cursor[i] = r;
}

// scatter src indices into CSR buckets
__global__ void k_scatter(const void* __restrict__ ei, int E) {
    int i = blockIdx.x * blockDim.x + threadIdx.x;
    if (i >= E) return;
    int src, dst;
    if (g_is64) {
        const long long* p = (const long long*)ei;
        src = (int)p[i]; dst = (int)p[E + i];
    } else {
        const int* p = (const int*)ei;
        src = p[i]; dst = p[E + i];
    }
    int pos = atomicAdd(&g_cursor[dst], 1);
    g_esrc[pos] = src;
}

// one warp per dst node, x-space aggregation: 32B gather per edge.
// lane: g = lane>>3 (head), owns x components 2i,2i+1 (i = lane&7).
__global__ void k_agg(int N) {
    int tid = threadIdx.x;
    int node = (blockIdx.x * blockDim.x + tid) >> 5;
    int lane = tid & 31;
    if (node >= N) return;
    int g  = lane >> 3;
    int i2 = (lane & 7) * 2;

    const float*  asrc = g_asrc;
    const __half* x16  = g_x16;

    float advh = g_adst[node * NH + g];
    // self-loop
    float pself = __expf(lrelu02(asrc[node * NH + g] + advh));
    float2 xf = __half22float2(*(const __half2*)&x16[node * 16 + i2]);
    float a0 = pself * xf.x, a1 = pself * xf.y;
    float dsum = pself;

    int j   = g_rowst[node];
    int end = j + g_deg[node];
    for (; j + 4 <= end; j += 4) {
        int s0 = g_esrc[j],     s1 = g_esrc[j + 1];
        int s2 = g_esrc[j + 2], s3 = g_esrc[j + 3];
        float e0 = asrc[s0 * NH + g], e1 = asrc[s1 * NH + g];
        float e2 = asrc[s2 * NH + g], e3 = asrc[s3 * NH + g];
        __half2 h0 = *(const __half2*)&x16[s0 * 16 + i2];
        __half2 h1 = *(const __half2*)&x16[s1 * 16 + i2];
        __half2 h2 = *(const __half2*)&x16[s2 * 16 + i2];
        __half2 h3 = *(const __half2*)&x16[s3 * 16 + i2];
        float p0 = __expf(lrelu02(e0 + advh));
        float p1 = __expf(lrelu02(e1 + advh));
        float p2 = __expf(lrelu02(e2 + advh));
        float p3 = __expf(lrelu02(e3 + advh));
        float2 f;
        f = __half22float2(h0); a0 += p0 * f.x; a1 += p0 * f.y;
        f = __half22float2(h1); a0 += p1 * f.x; a1 += p1 * f.y;
        f = __half22float2(h2); a0 += p2 * f.x; a1 += p2 * f.y;
        f = __half22float2(h3); a0 += p3 * f.x; a1 += p3 * f.y;
        dsum += p0 + p1 + p2 + p3;
    }
    for (; j < end; j++) {
        int s = g_esrc[j];
        float p = __expf(lrelu02(asrc[s * NH + g] + advh));
        float2 f = __half22float2(*(const __half2*)&x16[s * 16 + i2]);
        a0 += p * f.x; a1 += p * f.y;
        dsum += p;
    }
    *(float2*)&g_accum[node * 64 + g * 16 + i2] = make_float2(a0, a1);
    if ((lane & 7) == 0) g_den[node * NH + g] = dsum;
}

// apply W (rank-16 -> 128 ch), normalize, batchnorm stats, store LUT rows.
// warp per node; lane owns channels lane*4..lane*4+3; W kept in registers.
__global__ void k_post(const float* __restrict__ Wl, int N) {
    __shared__ float ssum[HC], ssq[HC];
    int tid = threadIdx.x;
    if (tid < HC) { ssum[tid] = 0.f; ssq[tid] = 0.f; }
    int lane = tid & 31;
    int warp = tid >> 5;
    int g = lane >> 3;

    float4 Wr[16];
#pragma unroll
    for (int k = 0; k < 16; k++)
        Wr[k] = ((const float4*)Wl)[k * 32 + lane];
    __syncthreads();

    float ls0 = 0.f, ls1 = 0.f, ls2 = 0.f, ls3 = 0.f;
    float lq0 = 0.f, lq1 = 0.f, lq2 = 0.f, lq3 = 0.f;

    for (int node = blockIdx.x * 8 + warp; node < N; node += gridDim.x * 8) {
        const float4* ap = (const float4*)&g_accum[node * 64 + g * 16];
        float cv[16];
        *(float4*)&cv[0]  = ap[0];
        *(float4*)&cv[4]  = ap[1];
        *(float4*)&cv[8]  = ap[2];
        *(float4*)&cv[12] = ap[3];
        float inv = 1.f / g_den[node * NH + g];
        float4 o = make_float4(0.f, 0.f, 0.f, 0.f);
#pragma unroll
        for (int k = 0; k < 16; k++) {
            o.x += cv[k] * Wr[k].x; o.y += cv[k] * Wr[k].y;
            o.z += cv[k] * Wr[k].z; o.w += cv[k] * Wr[k].w;
        }
        o.x *= inv; o.y *= inv; o.z *= inv; o.w *= inv;
        int lp = g_isl[node];
        if (lp) ((float4*)g_embed)[(lp - 1) * 32 + lane] = o;
        ls0 += o.x; ls1 += o.y; ls2 += o.z; ls3 += o.w;
        lq0 += o.x * o.x; lq1 += o.y * o.y; lq2 += o.z * o.z; lq3 += o.w * o.w;
    }
    int c = lane * 4;
    atomicAdd(&ssum[c + 0], ls0); atomicAdd(&ssq[c + 0], lq0);
    atomicAdd(&ssum[c + 1], ls1); atomicAdd(&ssq[c + 1], lq1);
    atomicAdd(&ssum[c + 2], ls2); atomicAdd(&ssq[c + 2], lq2);
    atomicAdd(&ssum[c + 3], ls3); atomicAdd(&ssq[c + 3], lq3);
    __syncthreads();
    if (tid < HC) {
        atomicAdd(&g_sum[tid],   ssum[tid]);
        atomicAdd(&g_sumsq[tid], ssq[tid]);
    }
}

// batchnorm+relu on embed rows, MLP 128->32->1. (bias_gat cancels in BN.)
__global__ void k_final(const float* __restrict__ gamma,
                        const float* __restrict__ beta,
                        const float* __restrict__ W1, const float* __restrict__ b1,
                        const float* __restrict__ W2, const float* __restrict__ b2,
                        float* __restrict__ out, int N) {
    __shared__ float se[128];
    __shared__ float sz[32];
    int c = threadIdx.x;
    float invN = 1.f / (float)N;
    float mean = g_sum[c] * invN;
    float var  = g_sumsq[c] * invN - mean * mean;
    float v = g_embed[blockIdx.x * HC + c];
    float e = (v - mean) * rsqrtf(var + 1e-5f) * gamma[c] + beta[c];
    se[c] = fmaxf(e, 0.f);
    __syncthreads();
    if (c < 32) {
        float acc = b1[c];
#pragma unroll 8
        for (int k = 0; k < 128; k++) acc += se[k] * W1[k * 32 + c];
        sz[c] = acc > 0.f ? acc : 0.01f * acc;
    }
    __syncthreads();
    if (c == 0) {
        float acc = b2[0];
#pragma unroll
        for (int j = 0; j < 32; j++) acc += sz[j] * W2[j];
        out[blockIdx.x] = acc;
    }
}

// ---------------- launch --------------------------------------------------
extern "C" void kernel_launch(void* const* d_in, const int* in_sizes, int n_in,
                              void* d_out, int out_size) {
    const float* x     = (const float*)d_in[0];
    const void*  ei    = d_in[1];
    const int*   lut   = (const int*)d_in[2];
    const float* Wl    = (const float*)d_in[3];
    const float* att_s = (const float*)d_in[4];
    const float* att_d = (const float*)d_in[5];
    const float* gamma = (const float*)d_in[7];
    const float* beta  = (const float*)d_in[8];
    const float* W1    = (const float*)d_in[9];
    const float* b1    = (const float*)d_in[10];
    const float* W2    = (const float*)d_in[11];
    const float* b2    = (const float*)d_in[12];

    int N  = in_sizes[0] / 16;
    int E  = in_sizes[1] / 2;
    int NL = in_sizes[2];
    int nbScan = (N + 1023) / 1024;
    int nLin   = (N + 255) / 256;
    int nHist  = (E + 255) / 256;

    k_init   <<<nLin, 256>>>((const int*)ei, Wl, att_s, att_d, N);
    k_linhist<<<nLin + nHist, 256>>>(x, ei, N, E, nLin);
    k_scanA  <<<nbScan, 1024>>>(N);
    k_scanB  <<<1, 128>>>(nbScan);
    k_scanC  <<<nLin, 256>>>(lut, N, NL);
    k_scatter<<<nHist, 256>>>(ei, E);
    k_agg    <<<(N * 32 + 255) / 256, 256>>>(N);
    k_post   <<<592, 256>>>(Wl, N);
    k_final  <<<NL, 128>>>(gamma, beta, W1, b1, W2, b2, (float*)d_out, N);
}

// round 6
// speedup vs baseline: 4.1009x; 1.0840x over previous
#include <cuda_runtime.h>
#include <cuda_fp16.h>
#include <math.h>
#include <float.h>

#define NMAX 100000
#define EMAX 1700000
#define HC   128
#define NH   4

// ---------------- static device scratch ----------------------------------
__device__ __half g_x16 [NMAX * 16];   // x in fp16 (3.2 MB, L2-resident)
__device__ float g_asrc [NMAX * NH];
__device__ float g_adst [NMAX * NH];
__device__ float g_embed[1024 * HC];   // LUT rows of GAT output
__device__ int   g_deg    [NMAX];
__device__ int   g_rowst  [NMAX];
__device__ int   g_cursor [NMAX];
__device__ int   g_isl    [NMAX];      // lut position + 1, or 0
__device__ long long g_state[128];     // lookback scan states (sum<<2 | flag)
__device__ int   g_esrc [EMAX];        // CSR payload: src only
__device__ float g_ws   [64];          // W @ att_src  (4 heads x 16)
__device__ float g_wd   [64];          // W @ att_dst
__device__ float g_sum  [HC];
__device__ float g_sumsq[HC];
__device__ int   g_is64;

__device__ __forceinline__ float lrelu02(float v) { return v > 0.f ? v : 0.2f * v; }

// ---------------- kernels ------------------------------------------------

// init + ws/wd precompute + dtype probe + scan-state reset
__global__ void k_init(const int* ei32, const float* __restrict__ Wl,
                       const float* __restrict__ att_s,
                       const float* __restrict__ att_d, int N) {
    int i = blockIdx.x * blockDim.x + threadIdx.x;
    if (i < N)   { g_deg[i] = 0; g_isl[i] = 0; }
    if (i < HC)  { g_sum[i] = 0.f; g_sumsq[i] = 0.f; }
    if (i < 128) g_state[i] = 0;
    if (blockIdx.x == 0 && threadIdx.x < 128) {
        int t = threadIdx.x;
        int h = (t & 63) >> 4, k = t & 15;
        const float* att = (t < 64) ? att_s : att_d;
        float s = 0.f;
        for (int c = 0; c < 32; c++)
            s += Wl[k * HC + h * 32 + c] * att[h * 32 + c];
        if (t < 64) g_ws[t] = s; else g_wd[t - 64] = s;
    }
    if (i == 0) {
        int all0 = 1;
        for (int k = 0; k < 128; k++)
            if (ei32[2 * k + 1] != 0) { all0 = 0; break; }
        g_is64 = all0;
    }
}

// Fused: blocks [0,nLin): per-thread node -> x16 + asrc/adst.
//        blocks [nLin,..): degree histogram, 2 edges per thread.
__global__ void k_linhist(const float* __restrict__ x,
                          const void* __restrict__ ei,
                          int N, int E, int nLin) {
    int tid = threadIdx.x;
    if (blockIdx.x >= nLin) {
        int e0 = ((blockIdx.x - nLin) * blockDim.x + tid) * 2;
        if (e0 < E) {
            int is64 = g_is64;
            int d0, d1 = -1;
            if (is64) {
                const long long* p = (const long long*)ei;
                d0 = (int)p[E + e0];
                if (e0 + 1 < E) d1 = (int)p[E + e0 + 1];
            } else {
                const int* p = (const int*)ei;
                d0 = p[E + e0];
                if (e0 + 1 < E) d1 = p[E + e0 + 1];
            }
            atomicAdd(&g_deg[d0], 1);
            if (d1 >= 0) atomicAdd(&g_deg[d1], 1);
        }
        return;
    }
    __shared__ float sws[64], swd[64];
    if (tid < 64)  sws[tid] = g_ws[tid];
    else if (tid < 128) swd[tid - 64] = g_wd[tid - 64];
    __syncthreads();

    int node = blockIdx.x * blockDim.x + tid;
    if (node >= N) return;
    float xf[16];
    const float4* xr = (const float4*)(x + node * 16);
#pragma unroll
    for (int q = 0; q < 4; q++) {
        float4 v = xr[q];
        xf[q * 4 + 0] = v.x; xf[q * 4 + 1] = v.y;
        xf[q * 4 + 2] = v.z; xf[q * 4 + 3] = v.w;
    }
    __half hx[16];
#pragma unroll
    for (int k = 0; k < 16; k++) hx[k] = __float2half_rn(xf[k]);
    ((uint4*)g_x16)[node * 2 + 0] = *(uint4*)&hx[0];
    ((uint4*)g_x16)[node * 2 + 1] = *(uint4*)&hx[8];
    float4 as, ad;
    float* asp = (float*)&as; float* adp = (float*)&ad;
#pragma unroll
    for (int h = 0; h < 4; h++) {
        float ss = 0.f, sd = 0.f;
#pragma unroll
        for (int k = 0; k < 16; k++) {
            ss += xf[k] * sws[h * 16 + k];
            sd += xf[k] * swd[h * 16 + k];
        }
        asp[h] = ss; adp[h] = sd;
    }
    ((float4*)g_asrc)[node] = as;
    ((float4*)g_adst)[node] = ad;
}

// single-pass decoupled-lookback exclusive scan of g_deg -> g_rowst/g_cursor.
// All blocks co-resident (grid <= 98 < 148 SMs) so spin lookback is safe.
// Also marks LUT positions.
__global__ void k_scan(const int* __restrict__ lut, int N, int NL) {
    __shared__ int s[1024];
    __shared__ int s_prefix;
    int bid = blockIdx.x;
    int t = threadIdx.x;
    int i = bid * 1024 + t;
    if (i < NL) g_isl[lut[i]] = i + 1;

    int v = (i < N) ? g_deg[i] : 0;
    s[t] = v;
    __syncthreads();
#pragma unroll
    for (int off = 1; off < 1024; off <<= 1) {
        int u = (t >= off) ? s[t - off] : 0;
        __syncthreads();
        s[t] += u;
        __syncthreads();
    }
    int incl = s[t];
    int blocksum = s[1023];

    if (t == 0) {
        long long pub = (bid == 0)
            ? (((long long)blocksum << 2) | 2)     // block 0: final prefix
            : (((long long)blocksum << 2) | 1);    // aggregate
        atomicExch((unsigned long long*)&g_state[bid], (unsigned long long)pub);
    }
    if (bid == 0) { if (t == 0) s_prefix = 0; }
    else if (t < 32) {
        long long acc = 0;
        int look = bid - 1;
        while (true) {
            int idx = look - t;
            long long st = (idx >= 0)
                ? *(volatile long long*)&g_state[idx]
                : 2LL;                               // virtual prefix 0
            int flag = (int)(st & 3);
            if (__all_sync(0xffffffffu, flag != 0)) {
                unsigned pm = __ballot_sync(0xffffffffu, flag == 2);
                if (pm) {
                    int steps = __ffs(pm) - 1;       // nearest prefix
                    long long val = (t <= steps) ? (st >> 2) : 0;
#pragma unroll
                    for (int o = 16; o; o >>= 1)
                        val += __shfl_down_sync(0xffffffffu, val, o);
                    if (t == 0) acc += val;
                    break;
                } else {
                    long long val = st >> 2;
#pragma unroll
                    for (int o = 16; o; o >>= 1)
                        val += __shfl_down_sync(0xffffffffu, val, o);
                    if (t == 0) acc += val;
                    look -= 32;
                }
            }
        }
        if (t == 0) {
            s_prefix = (int)acc;
            long long pub = (((acc + blocksum) << 2) | 2);
            atomicExch((unsigned long long*)&g_state[bid], (unsigned long long)pub);
        }
    }
    __syncthreads();
    if (i < N) {
        int r = s_prefix + incl - v;
        g_rowst[i]  = r;
        g_cursor[i] = r;
    }
}

// scatter src indices into CSR buckets, 2 edges per thread
__global__ void k_scatter(const void* __restrict__ ei, int E) {
    int e0 = (blockIdx.x * blockDim.x + threadIdx.x) * 2;
    if (e0 >= E) return;
    int is64 = g_is64;
    int s0, d0, s1 = 0, d1 = -1;
    if (is64) {
        const long long* p = (const long long*)ei;
        s0 = (int)p[e0]; d0 = (int)p[E + e0];
        if (e0 + 1 < E) { s1 = (int)p[e0 + 1]; d1 = (int)p[E + e0 + 1]; }
    } else {
        const int* p = (const int*)ei;
        s0 = p[e0]; d0 = p[E + e0];
        if (e0 + 1 < E) { s1 = p[e0 + 1]; d1 = p[E + e0 + 1]; }
    }
    int pos0 = atomicAdd(&g_cursor[d0], 1);
    g_esrc[pos0] = s0;
    if (d1 >= 0) {
        int pos1 = atomicAdd(&g_cursor[d1], 1);
        g_esrc[pos1] = s1;
    }
}

// Fused aggregate + W-apply + normalize + BN stats + LUT row store.
// One warp per node (grid-strided, ~1 resident wave). x-space gather 8B/lane.
// After the edge loop, lane redistributes the 16 per-head accumulator
// components via shfl and applies W (shared, 8KB) to its 4 output channels.
__global__ void k_aggpost(const float* __restrict__ Wl, int N) {
    __shared__ float4 sW[16 * 32];          // 8 KB
    __shared__ float ssum[HC], ssq[HC];
    int tid = threadIdx.x;
    for (int i = tid; i < 512; i += blockDim.x)
        sW[i] = ((const float4*)Wl)[i];
    if (tid < HC) { ssum[tid] = 0.f; ssq[tid] = 0.f; }
    __syncthreads();

    int lane = tid & 31;
    int warp = tid >> 5;
    int g  = lane >> 3;
    int i2 = (lane & 7) * 2;

    const float*  asrc = g_asrc;
    const __half* x16  = g_x16;

    float bs0 = 0.f, bs1 = 0.f, bs2 = 0.f, bs3 = 0.f;
    float bq0 = 0.f, bq1 = 0.f, bq2 = 0.f, bq3 = 0.f;

    for (int node = blockIdx.x * 8 + warp; node < N; node += gridDim.x * 8) {
        float advh = asrc == 0 ? 0.f : g_adst[node * NH + g];  // keep simple load
        // self-loop
        float pself = __expf(lrelu02(asrc[node * NH + g] + advh));
        float2 xf = __half22float2(*(const __half2*)&x16[node * 16 + i2]);
        float a0 = pself * xf.x, a1 = pself * xf.y;
        float dsum = pself;

        int j   = g_rowst[node];
        int end = j + g_deg[node];
        for (; j + 4 <= end; j += 4) {
            int s0 = g_esrc[j],     s1 = g_esrc[j + 1];
            int s2 = g_esrc[j + 2], s3 = g_esrc[j + 3];
            float e0 = asrc[s0 * NH + g], e1 = asrc[s1 * NH + g];
            float e2 = asrc[s2 * NH + g], e3 = asrc[s3 * NH + g];
            __half2 h0 = *(const __half2*)&x16[s0 * 16 + i2];
            __half2 h1 = *(const __half2*)&x16[s1 * 16 + i2];
            __half2 h2 = *(const __half2*)&x16[s2 * 16 + i2];
            __half2 h3 = *(const __half2*)&x16[s3 * 16 + i2];
            float p0 = __expf(lrelu02(e0 + advh));
            float p1 = __expf(lrelu02(e1 + advh));
            float p2 = __expf(lrelu02(e2 + advh));
            float p3 = __expf(lrelu02(e3 + advh));
            float2 f;
            f = __half22float2(h0); a0 += p0 * f.x; a1 += p0 * f.y;
            f = __half22float2(h1); a0 += p1 * f.x; a1 += p1 * f.y;
            f = __half22float2(h2); a0 += p2 * f.x; a1 += p2 * f.y;
            f = __half22float2(h3); a0 += p3 * f.x; a1 += p3 * f.y;
            dsum += p0 + p1 + p2 + p3;
        }
        for (; j < end; j++) {
            int s = g_esrc[j];
            float p = __expf(lrelu02(asrc[s * NH + g] + advh));
            float2 f = __half22float2(*(const __half2*)&x16[s * 16 + i2]);
            a0 += p * f.x; a1 += p * f.y;
            dsum += p;
        }
        float inv = 1.f / dsum;

        // redistribute accumulators within head group and apply W
        float o0 = 0.f, o1 = 0.f, o2 = 0.f, o3 = 0.f;
#pragma unroll
        for (int k = 0; k < 16; k++) {
            float w = __shfl_sync(0xffffffffu, (k & 1) ? a1 : a0,
                                  (g << 3) + (k >> 1));
            float4 W4 = sW[k * 32 + lane];
            o0 += w * W4.x; o1 += w * W4.y;
            o2 += w * W4.z; o3 += w * W4.w;
        }
        o0 *= inv; o1 *= inv; o2 *= inv; o3 *= inv;

        int lp = g_isl[node];
        if (lp) ((float4*)g_embed)[(lp - 1) * 32 + lane] =
                    make_float4(o0, o1, o2, o3);
        bs0 += o0; bs1 += o1; bs2 += o2; bs3 += o3;
        bq0 += o0 * o0; bq1 += o1 * o1; bq2 += o2 * o2; bq3 += o3 * o3;
    }
    int c = lane * 4;
    atomicAdd(&ssum[c + 0], bs0); atomicAdd(&ssq[c + 0], bq0);
    atomicAdd(&ssum[c + 1], bs1); atomicAdd(&ssq[c + 1], bq1);
    atomicAdd(&ssum[c + 2], bs2); atomicAdd(&ssq[c + 2], bq2);
    atomicAdd(&ssum[c + 3], bs3); atomicAdd(&ssq[c + 3], bq3);
    __syncthreads();
    if (tid < HC) {
        atomicAdd(&g_sum[tid],   ssum[tid]);
        atomicAdd(&g_sumsq[tid], ssq[tid]);
    }
}

// batchnorm+relu on embed rows, MLP 128->32->1. (bias_gat cancels in BN.)
__global__ void k_final(const float* __restrict__ gamma,
                        const float* __restrict__ beta,
                        const float* __restrict__ W1, const float* __restrict__ b1,
                        const float* __restrict__ W2, const float* __restrict__ b2,
                        float* __restrict__ out, int N) {
    __shared__ float se[128];
    __shared__ float sz[32];
    int c = threadIdx.x;
    float invN = 1.f / (float)N;
    float mean = g_sum[c] * invN;
    float var  = g_sumsq[c] * invN - mean * mean;
    float v = g_embed[blockIdx.x * HC + c];
    float e = (v - mean) * rsqrtf(var + 1e-5f) * gamma[c] + beta[c];
    se[c] = fmaxf(e, 0.f);
    __syncthreads();
    if (c < 32) {
        float acc = b1[c];
#pragma unroll 8
        for (int k = 0; k < 128; k++) acc += se[k] * W1[k * 32 + c];
        sz[c] = acc > 0.f ? acc : 0.01f * acc;
    }
    __syncthreads();
    if (c == 0) {
        float acc = b2[0];
#pragma unroll
        for (int j = 0; j < 32; j++) acc += sz[j] * W2[j];
        out[blockIdx.x] = acc;
    }
}

// ---------------- launch --------------------------------------------------
extern "C" void kernel_launch(void* const* d_in, const int* in_sizes, int n_in,
                              void* d_out, int out_size) {
    const float* x     = (const float*)d_in[0];
    const void*  ei    = d_in[1];
    const int*   lut   = (const int*)d_in[2];
    const float* Wl    = (const float*)d_in[3];
    const float* att_s = (const float*)d_in[4];
    const float* att_d = (const float*)d_in[5];
    const float* gamma = (const float*)d_in[7];
    const float* beta  = (const float*)d_in[8];
    const float* W1    = (const float*)d_in[9];
    const float* b1    = (const float*)d_in[10];
    const float* W2    = (const float*)d_in[11];
    const float* b2    = (const float*)d_in[12];

    int N  = in_sizes[0] / 16;
    int E  = in_sizes[1] / 2;
    int NL = in_sizes[2];
    int nbScan = (N + 1023) / 1024;
    int nLin   = (N + 255) / 256;
    int nHist2 = (E + 511) / 512;

    k_init   <<<nLin, 256>>>((const int*)ei, Wl, att_s, att_d, N);
    k_linhist<<<nLin + nHist2, 256>>>(x, ei, N, E, nLin);
    k_scan   <<<nbScan, 1024>>>(lut, N, NL);
    k_scatter<<<nHist2, 256>>>(ei, E);
    k_aggpost<<<1184, 256>>>(Wl, N);
    k_final  <<<NL, 128>>>(gamma, beta, W1, b1, W2, b2, (float*)d_out, N);
}